// round 10
// baseline (speedup 1.0000x reference)
#include <cuda_runtime.h>
#include <cuda_bf16.h>
#include <math.h>

// ---------------- problem constants ----------------
#define N0_NODES 20000
#define N_ALL    40000
#define F0_DIM   512
#define HID      64
#define NHEAD    8
#define E_CNT    200000
#define BATCH    8192
#define AV_DIM   128
#define CH_DIM   128

typedef unsigned long long ull;

__device__ __forceinline__ ull pack2(float lo, float hi) {
    ull r; asm("mov.b64 %0, {%1, %2};" : "=l"(r) : "f"(lo), "f"(hi)); return r;
}
__device__ __forceinline__ void unpack2(ull v, float& lo, float& hi) {
    asm("mov.b64 {%0, %1}, %2;" : "=f"(lo), "=f"(hi) : "l"(v));
}
__device__ __forceinline__ void ffma2(ull& d, ull a, ull b) {
    asm("fma.rn.f32x2 %0, %1, %2, %0;" : "+l"(d) : "l"(a), "l"(b));
}
__device__ __forceinline__ float tanh_fast(float x) {
    float y; asm("tanh.approx.f32 %0, %1;" : "=f"(y) : "f"(x)); return y;
}
__device__ __forceinline__ void cpa16(unsigned dst, const float* src, bool valid) {
    int sz = valid ? 16 : 0;
    asm volatile("cp.async.cg.shared.global [%0], [%1], 16, %2;" :: "r"(dst), "l"(src), "r"(sz));
}
#define CP_COMMIT() asm volatile("cp.async.commit_group;")
#define CP_WAIT0()  asm volatile("cp.async.wait_group 0;")

// ---------------- device scratch ----------------
__device__ __align__(16) float g_feat[N_ALL * HID];
__device__ __align__(16) float g_fr[4 * 3 * HID];
__device__ __align__(16) float g_s[4 * BATCH * NHEAD];
__device__ __align__(16) float g_ret[4 * BATCH * HID];
__device__ __align__(16) float g_mpout[4 * BATCH * HID];
__device__ __align__(16) float g_sem[4];

// ---------------- rotation precompute ----------------
__global__ void k_fr(const float* __restrict__ r_vec) {
    int tid = threadIdx.x;
    if (tid >= 128) return;
    int mp = tid >> 5, c = tid & 31;
    int et0 = (mp < 2) ? 0 : 1;
    int et1 = (mp < 2) ? 1 : 0;

    float x0 = r_vec[(et1 >> 1) * 64 + 2 * c], y0 = r_vec[(et1 >> 1) * 64 + 2 * c + 1];
    float n = rsqrtf(x0 * x0 + y0 * y0);
    float f1re = x0 * n, f1im = (et1 & 1) ? -y0 * n : y0 * n;

    float x1 = r_vec[(et0 >> 1) * 64 + 2 * c], y1 = r_vec[(et0 >> 1) * 64 + 2 * c + 1];
    n = rsqrtf(x1 * x1 + y1 * y1);
    float r0re = x1 * n, r0im = (et0 & 1) ? -y1 * n : y1 * n;

    float f0re = f1re * r0re - f1im * r0im;
    float f0im = f1re * r0im + f1im * r0re;

    float* base = g_fr + mp * (3 * HID);
    base[0 * HID + 2 * c] = f0re; base[0 * HID + 2 * c + 1] = f0im;
    base[1 * HID + 2 * c] = f1re; base[1 * HID + 2 * c + 1] = f1im;
    base[2 * HID + 2 * c] = 1.f;  base[2 * HID + 2 * c + 1] = 0.f;
}

// ---------------- feature towers v2: K-split f32x2, LDS.128 both operands ----------------
// Block 256 = 16 tx * 16 ty. TOW_BM=64 rows/block. Thread tile: 4 rows x 4 cols.
// acc[i][j] is f32x2 with lo = even-k partial, hi = odd-k partial; z = lo + hi.
// xs: [row][k] pitch 68 (272B: 16B-aligned, lane-stride 272 % 128 = 16 -> conflict-free .128)
// wsT: [col][k] pitch 68 (same property). wsT filled by register-staged transpose of pw/w2.
#define TOW_BM   64
#define TP       68
#define XS_SZ    (TOW_BM * TP)
#define WS_SZ    (64 * TP)
#define TOW_SMEM ((2 * XS_SZ + 2 * WS_SZ) * 4)

__device__ __forceinline__ float gelu_exact(float z) {
    return 0.5f * z * (1.f + erff(z * 0.70710678118654752f));
}

__global__ void __launch_bounds__(256, 2) k_tower(
    const float* __restrict__ f0, const float* __restrict__ f1,
    const float* __restrict__ pw0, const float* __restrict__ pb0,
    const float* __restrict__ w20, const float* __restrict__ b20,
    const float* __restrict__ gm0, const float* __restrict__ be0,
    const float* __restrict__ pw1, const float* __restrict__ pb1,
    const float* __restrict__ w21, const float* __restrict__ b21,
    const float* __restrict__ gm1, const float* __restrict__ be1,
    const int* __restrict__ idx0, const int* __restrict__ idx1)
{
    int t = blockIdx.y;
    const float* feats = t ? f1  : f0;
    const float* pw    = t ? pw1 : pw0;
    const float* pb    = t ? pb1 : pb0;
    const float* w2    = t ? w21 : w20;
    const float* b2    = t ? b21 : b20;
    const float* gmw   = t ? gm1 : gm0;
    const float* bew   = t ? be1 : be0;
    const int*   idx   = t ? idx1 : idx0;

    extern __shared__ float sm[];
    float* xsp[2] = { sm, sm + XS_SZ };
    float* wsp[2] = { sm + 2 * XS_SZ, sm + 2 * XS_SZ + WS_SZ };
    unsigned smem_u32 = (unsigned)__cvta_generic_to_shared(sm);
    unsigned xsa[2] = { smem_u32, smem_u32 + XS_SZ * 4 };

    int tid = threadIdx.x;
    int tx = tid & 15, ty = tid >> 4;
    int ty4 = ty * 4, tx4 = tx * 4;
    int nb = blockIdx.x * TOW_BM;

    // w-prefetch thread mapping: k0 = (tid&15)*4, c0w = (tid>>4)*4  (coalesced-ish LDG, 2-way STS)
    int wk0 = (tid & 15) * 4, wc0 = (tid >> 4) * 4;

    auto prefetch_x = [&](int kc, int b) {
        #pragma unroll
        for (int r = 0; r < 4; ++r) {
            int i = tid + r * 256;
            int node = i >> 4, kq = i & 15;
            int ng = nb + node;
            cpa16(xsa[b] + (unsigned)(node * TP + kq * 4) * 4,
                  feats + (size_t)ng * F0_DIM + kc + kq * 4, ng < N0_NODES);
        }
        CP_COMMIT();
    };
    auto ldg_w = [&](const float* wsrc, int kc, float4* wreg) {
        #pragma unroll
        for (int kk = 0; kk < 4; ++kk)
            wreg[kk] = *(const float4*)(wsrc + (size_t)(kc + wk0 + kk) * HID + wc0);
    };
    auto sts_wT = [&](int b, const float4* wreg) {
        float* ws = wsp[b];
        #pragma unroll
        for (int kk = 0; kk < 4; ++kk) {
            ws[(wc0 + 0) * TP + wk0 + kk] = wreg[kk].x;
            ws[(wc0 + 1) * TP + wk0 + kk] = wreg[kk].y;
            ws[(wc0 + 2) * TP + wk0 + kk] = wreg[kk].z;
            ws[(wc0 + 3) * TP + wk0 + kk] = wreg[kk].w;
        }
    };

    ull acc[4][4];
    #pragma unroll
    for (int i = 0; i < 4; ++i)
        #pragma unroll
        for (int j = 0; j < 4; ++j) acc[i][j] = 0ull;

    float4 wreg[4];

    // prologue: chunk 0 x + w
    prefetch_x(0, 0);
    ldg_w(pw, 0, wreg);
    CP_WAIT0();
    sts_wT(0, wreg);
    __syncthreads();

    float4 w2reg[4];

    // ---- GEMM1: z = x @ pw ----
    for (int c = 0; c < 8; ++c) {
        int b = c & 1;
        if (c < 7) {
            prefetch_x((c + 1) * 64, b ^ 1);
            ldg_w(pw, (c + 1) * 64, wreg);
        } else {
            ldg_w(w2, 0, w2reg);   // prefetch w2 during last chunk
        }

        const float* xs = xsp[b];
        const float* ws = wsp[b];
        #pragma unroll 2
        for (int k = 0; k < 64; k += 4) {
            ulonglong2 xv[4], wv[4];
            #pragma unroll
            for (int i = 0; i < 4; ++i)
                xv[i] = *(const ulonglong2*)(xs + (ty4 + i) * TP + k);
            #pragma unroll
            for (int j = 0; j < 4; ++j)
                wv[j] = *(const ulonglong2*)(ws + (tx4 + j) * TP + k);
            #pragma unroll
            for (int i = 0; i < 4; ++i)
                #pragma unroll
                for (int j = 0; j < 4; ++j) {
                    ffma2(acc[i][j], xv[i].x, wv[j].x);
                    ffma2(acc[i][j], xv[i].y, wv[j].y);
                }
        }

        if (c < 7) {
            CP_WAIT0();
            __syncthreads();          // xs[b^1] ready; wsT[b^1] safe to overwrite
            sts_wT(b ^ 1, wreg);
            __syncthreads();
        }
    }

    // ---- z, GELU -> xs[0]; w2T -> wsT[0] ----
    float4 pbv = *(const float4*)(pb + tx4);
    float z[4][4];
    #pragma unroll
    for (int i = 0; i < 4; ++i) {
        float lo, hi;
        unpack2(acc[i][0], lo, hi); z[i][0] = lo + hi + pbv.x;
        unpack2(acc[i][1], lo, hi); z[i][1] = lo + hi + pbv.y;
        unpack2(acc[i][2], lo, hi); z[i][2] = lo + hi + pbv.z;
        unpack2(acc[i][3], lo, hi); z[i][3] = lo + hi + pbv.w;
        acc[i][0] = acc[i][1] = acc[i][2] = acc[i][3] = 0ull;
    }
    __syncthreads();   // all reads of xs[1]/wsT[1] done; chunk-7 consumed
    #pragma unroll
    for (int i = 0; i < 4; ++i) {
        float4 h4;
        h4.x = gelu_exact(z[i][0]);
        h4.y = gelu_exact(z[i][1]);
        h4.z = gelu_exact(z[i][2]);
        h4.w = gelu_exact(z[i][3]);
        *(float4*)(xsp[0] + (ty4 + i) * TP + tx4) = h4;
    }
    sts_wT(0, w2reg);
    __syncthreads();

    // ---- GEMM2: y = h @ w2 + b2 + z ----
    {
        const float* xs = xsp[0];
        const float* ws = wsp[0];
        #pragma unroll 2
        for (int k = 0; k < 64; k += 4) {
            ulonglong2 xv[4], wv[4];
            #pragma unroll
            for (int i = 0; i < 4; ++i)
                xv[i] = *(const ulonglong2*)(xs + (ty4 + i) * TP + k);
            #pragma unroll
            for (int j = 0; j < 4; ++j)
                wv[j] = *(const ulonglong2*)(ws + (tx4 + j) * TP + k);
            #pragma unroll
            for (int i = 0; i < 4; ++i)
                #pragma unroll
                for (int j = 0; j < 4; ++j) {
                    ffma2(acc[i][j], xv[i].x, wv[j].x);
                    ffma2(acc[i][j], xv[i].y, wv[j].y);
                }
        }
    }

    float4 b2v = *(const float4*)(b2 + tx4);
    float y[4][4];
    #pragma unroll
    for (int i = 0; i < 4; ++i) {
        float lo, hi;
        unpack2(acc[i][0], lo, hi); y[i][0] = lo + hi + b2v.x + z[i][0];
        unpack2(acc[i][1], lo, hi); y[i][1] = lo + hi + b2v.y + z[i][1];
        unpack2(acc[i][2], lo, hi); y[i][2] = lo + hi + b2v.z + z[i][2];
        unpack2(acc[i][3], lo, hi); y[i][3] = lo + hi + b2v.w + z[i][3];
    }

    // ---- LayerNorm: reduce across 16 tx lanes (offsets 8,4,2,1 stay in half) ----
    float4 gv = *(const float4*)(gmw + tx4);
    float4 bev = *(const float4*)(bew + tx4);
    #pragma unroll
    for (int i = 0; i < 4; ++i) {
        float s1 = y[i][0] + y[i][1] + y[i][2] + y[i][3];
        float s2 = y[i][0] * y[i][0] + y[i][1] * y[i][1] + y[i][2] * y[i][2] + y[i][3] * y[i][3];
        #pragma unroll
        for (int o = 8; o > 0; o >>= 1) {
            s1 += __shfl_xor_sync(0xffffffffu, s1, o);
            s2 += __shfl_xor_sync(0xffffffffu, s2, o);
        }
        float mu  = s1 * (1.f / 64.f);
        float var = s2 * (1.f / 64.f) - mu * mu;
        float rs  = rsqrtf(var + 1e-5f);
        int ng = nb + ty4 + i;
        if (ng < N0_NODES) {
            int dst = idx[ng];
            float4 o4;
            o4.x = (y[i][0] - mu) * rs * gv.x + bev.x;
            o4.y = (y[i][1] - mu) * rs * gv.y + bev.y;
            o4.z = (y[i][2] - mu) * rs * gv.z + bev.z;
            o4.w = (y[i][3] - mu) * rs * gv.w + bev.w;
            *(float4*)(g_feat + (size_t)dst * HID + tx4) = o4;
        }
    }
}

// ---------------- metapath gather (per-mp launch): 2 instances per thread ----------------
__global__ void k_metapath(
    int mp,
    const int* __restrict__ emi, const int* __restrict__ tgt,
    const float* __restrict__ attn)
{
    int tid  = threadIdx.x;
    int sub  = tid & 15;
    int instA = blockIdx.x * 16 + (tid >> 4);
    int instB = instA + E_CNT / 2;

    const float4* fr4 = (const float4*)g_fr + mp * 48;
    float4 fr0 = fr4[sub], fr1 = fr4[16 + sub], fr2 = fr4[32 + sub];
    float4 av = ((const float4*)attn)[sub];

    int a0 = __ldg(emi + instA * 3);
    int a1 = __ldg(emi + instA * 3 + 1);
    int a2 = __ldg(emi + instA * 3 + 2);
    int b0i = __ldg(emi + instB * 3);
    int b1i = __ldg(emi + instB * 3 + 1);
    int b2i = __ldg(emi + instB * 3 + 2);
    int tA = __ldg(tgt + instA);
    int tB = __ldg(tgt + instB);

    const float4* feat4 = (const float4*)g_feat;
    float4 vA0 = __ldg(feat4 + (size_t)a0 * 16 + sub);
    float4 vA1 = __ldg(feat4 + (size_t)a1 * 16 + sub);
    float4 vA2 = __ldg(feat4 + (size_t)a2 * 16 + sub);
    float4 vB0 = __ldg(feat4 + (size_t)b0i * 16 + sub);
    float4 vB1 = __ldg(feat4 + (size_t)b1i * 16 + sub);
    float4 vB2 = __ldg(feat4 + (size_t)b2i * 16 + sub);

    const float inv3 = (1.f / 3.f);

    {
        float hx = (vA0.x * fr0.x - vA0.y * fr0.y) + (vA1.x * fr1.x - vA1.y * fr1.y) + (vA2.x * fr2.x - vA2.y * fr2.y);
        float hy = (vA0.x * fr0.y + vA0.y * fr0.x) + (vA1.x * fr1.y + vA1.y * fr1.x) + (vA2.x * fr2.y + vA2.y * fr2.x);
        float hz = (vA0.z * fr0.z - vA0.w * fr0.w) + (vA1.z * fr1.z - vA1.w * fr1.w) + (vA2.z * fr2.z - vA2.w * fr2.w);
        float hw = (vA0.z * fr0.w + vA0.w * fr0.z) + (vA1.z * fr1.w + vA1.w * fr1.z) + (vA2.z * fr2.w + vA2.w * fr2.z);
        hx *= inv3; hy *= inv3; hz *= inv3; hw *= inv3;

        float p = hx * av.x + hy * av.y + hz * av.z + hw * av.w;
        p += __shfl_xor_sync(0xffffffffu, p, 1);
        float e = p > 0.f ? p : 0.01f * p;
        float a = expf(e);

        size_t base = (size_t)mp * BATCH + tA;
        if (!(sub & 1)) atomicAdd(&g_s[base * NHEAD + (sub >> 1)], a);
        float* rb = g_ret + base * HID + sub * 4;
        asm volatile("red.global.add.v4.f32 [%0], {%1, %2, %3, %4};"
                     :: "l"(rb), "f"(a * hx), "f"(a * hy), "f"(a * hz), "f"(a * hw)
                     : "memory");
    }
    {
        float hx = (vB0.x * fr0.x - vB0.y * fr0.y) + (vB1.x * fr1.x - vB1.y * fr1.y) + (vB2.x * fr2.x - vB2.y * fr2.y);
        float hy = (vB0.x * fr0.y + vB0.y * fr0.x) + (vB1.x * fr1.y + vB1.y * fr1.x) + (vB2.x * fr2.y + vB2.y * fr2.x);
        float hz = (vB0.z * fr0.z - vB0.w * fr0.w) + (vB1.z * fr1.z - vB1.w * fr1.w) + (vB2.z * fr2.z - vB2.w * fr2.w);
        float hw = (vB0.z * fr0.w + vB0.w * fr0.z) + (vB1.z * fr1.w + vB1.w * fr1.z) + (vB2.z * fr2.w + vB2.w * fr2.z);
        hx *= inv3; hy *= inv3; hz *= inv3; hw *= inv3;

        float p = hx * av.x + hy * av.y + hz * av.z + hw * av.w;
        p += __shfl_xor_sync(0xffffffffu, p, 1);
        float e = p > 0.f ? p : 0.01f * p;
        float a = expf(e);

        size_t base = (size_t)mp * BATCH + tB;
        if (!(sub & 1)) atomicAdd(&g_s[base * NHEAD + (sub >> 1)], a);
        float* rb = g_ret + base * HID + sub * 4;
        asm volatile("red.global.add.v4.f32 [%0], {%1, %2, %3, %4};"
                     :: "l"(rb), "f"(a * hx), "f"(a * hy), "f"(a * hz), "f"(a * hw)
                     : "memory");
    }
}

// ---------------- fused normalize+elu+mpout + semantic GEMV (col-pair f32x2) ----------------
#define NSEM_BB  32
#define NSEM_BBP 33
#define NSEM_SMEM ((HID * AV_DIM + HID * NSEM_BBP) * 4)
__global__ void __launch_bounds__(256) k_normsem(
    int mp,
    const float* __restrict__ w1, const float* __restrict__ b1, const float* __restrict__ w2)
{
    int tid = threadIdx.x;
    extern __shared__ float dsm[];
    float* w1s = dsm;
    float* hs  = dsm + HID * AV_DIM;
    __shared__ float rbuf[8];

    for (int i = tid; i < HID * AV_DIM; i += 256) w1s[i] = w1[i];

    int b0 = blockIdx.x * NSEM_BB;
    #pragma unroll
    for (int r = 0; r < 8; ++r) {
        int i = tid + r * 256;
        int bl = i >> 6, k = i & 63;
        size_t row = (size_t)mp * BATCH + b0 + bl;
        float sv = g_s[row * NHEAD + (k >> 3)];
        float v = g_ret[row * HID + k] / (sv + 1e-9f);
        v = v > 0.f ? v : expf(v) - 1.f;
        g_mpout[row * HID + k] = v;
        hs[k * NSEM_BBP + bl] = v;
    }
    __syncthreads();

    int bl = tid & 31, ch = tid >> 5;
    int c0 = ch * 16;
    ull accp[8];
    {
        float4 ba = __ldg((const float4*)(b1 + c0));
        float4 bb = __ldg((const float4*)(b1 + c0 + 4));
        float4 bc = __ldg((const float4*)(b1 + c0 + 8));
        float4 bd = __ldg((const float4*)(b1 + c0 + 12));
        accp[0] = pack2(ba.x, ba.y); accp[1] = pack2(ba.z, ba.w);
        accp[2] = pack2(bb.x, bb.y); accp[3] = pack2(bb.z, bb.w);
        accp[4] = pack2(bc.x, bc.y); accp[5] = pack2(bc.z, bc.w);
        accp[6] = pack2(bd.x, bd.y); accp[7] = pack2(bd.z, bd.w);
    }
    #pragma unroll 4
    for (int k = 0; k < HID; ++k) {
        float xv = hs[k * NSEM_BBP + bl];
        ull xvp = pack2(xv, xv);
        const float4* wr = (const float4*)(w1s + k * AV_DIM + c0);
        float4 wv0 = wr[0], wv1 = wr[1], wv2 = wr[2], wv3 = wr[3];
        ffma2(accp[0], xvp, pack2(wv0.x, wv0.y));
        ffma2(accp[1], xvp, pack2(wv0.z, wv0.w));
        ffma2(accp[2], xvp, pack2(wv1.x, wv1.y));
        ffma2(accp[3], xvp, pack2(wv1.z, wv1.w));
        ffma2(accp[4], xvp, pack2(wv2.x, wv2.y));
        ffma2(accp[5], xvp, pack2(wv2.z, wv2.w));
        ffma2(accp[6], xvp, pack2(wv3.x, wv3.y));
        ffma2(accp[7], xvp, pack2(wv3.z, wv3.w));
    }
    float ssum = 0.f;
    {
        float4 wa = __ldg((const float4*)(w2 + c0));
        float4 wb = __ldg((const float4*)(w2 + c0 + 4));
        float4 wc = __ldg((const float4*)(w2 + c0 + 8));
        float4 wd = __ldg((const float4*)(w2 + c0 + 12));
        float lo, hi;
        unpack2(accp[0], lo, hi); ssum += tanh_fast(lo) * wa.x + tanh_fast(hi) * wa.y;
        unpack2(accp[1], lo, hi); ssum += tanh_fast(lo) * wa.z + tanh_fast(hi) * wa.w;
        unpack2(accp[2], lo, hi); ssum += tanh_fast(lo) * wb.x + tanh_fast(hi) * wb.y;
        unpack2(accp[3], lo, hi); ssum += tanh_fast(lo) * wb.z + tanh_fast(hi) * wb.w;
        unpack2(accp[4], lo, hi); ssum += tanh_fast(lo) * wc.x + tanh_fast(hi) * wc.y;
        unpack2(accp[5], lo, hi); ssum += tanh_fast(lo) * wc.z + tanh_fast(hi) * wc.w;
        unpack2(accp[6], lo, hi); ssum += tanh_fast(lo) * wd.x + tanh_fast(hi) * wd.y;
        unpack2(accp[7], lo, hi); ssum += tanh_fast(lo) * wd.z + tanh_fast(hi) * wd.w;
    }
    #pragma unroll
    for (int o = 16; o > 0; o >>= 1) ssum += __shfl_xor_sync(0xffffffffu, ssum, o);
    if ((tid & 31) == 0) rbuf[tid >> 5] = ssum;
    __syncthreads();
    if (tid == 0) {
        float t = rbuf[0] + rbuf[1] + rbuf[2] + rbuf[3] + rbuf[4] + rbuf[5] + rbuf[6] + rbuf[7];
        atomicAdd(&g_sem[mp], t);
    }
}

// ---------------- semantic fusion + product MLP + softmax ----------------
#define KF_BB  32
#define KF_BBP 33
#define KF_SMEM ((HID * CH_DIM + HID * KF_BBP + 2 * 8 * KF_BB) * 4)
__global__ void __launch_bounds__(256) k_final(
    const float* __restrict__ cw1, const float* __restrict__ cb1,
    const float* __restrict__ cw2, float* __restrict__ out)
{
    int tid = threadIdx.x;
    extern __shared__ float dsm[];
    float* cw1s = dsm;
    float* xs   = dsm + HID * CH_DIM;
    float* pl0  = xs + HID * KF_BBP;
    float* pl1  = pl0 + 8 * KF_BB;

    for (int i = tid; i < HID * CH_DIM; i += 256) cw1s[i] = cw1[i];

    float s0 = g_sem[0] * (1.f / BATCH), s1 = g_sem[1] * (1.f / BATCH);
    float s2 = g_sem[2] * (1.f / BATCH), s3 = g_sem[3] * (1.f / BATCH);
    float mU = fmaxf(s0, s1), mI = fmaxf(s2, s3);
    float e0 = expf(s0 - mU), e1 = expf(s1 - mU);
    float e2 = expf(s2 - mI), e3 = expf(s3 - mI);
    float bu0 = e0 / (e0 + e1), bu1 = e1 / (e0 + e1);
    float bi0 = e2 / (e2 + e3), bi1 = e3 / (e2 + e3);

    int b0 = blockIdx.x * KF_BB;
    #pragma unroll
    for (int r = 0; r < 8; ++r) {
        int i = tid + r * 256;
        int bl = i >> 6, k = i & 63;
        size_t b = b0 + bl;
        float hu = bu0 * g_mpout[((size_t)0 * BATCH + b) * HID + k]
                 + bu1 * g_mpout[((size_t)1 * BATCH + b) * HID + k];
        float hi = bi0 * g_mpout[((size_t)2 * BATCH + b) * HID + k]
                 + bi1 * g_mpout[((size_t)3 * BATCH + b) * HID + k];
        xs[k * KF_BBP + bl] = hu * hi;
    }
    __syncthreads();

    int bl = tid & 31, ch = tid >> 5;
    int c0 = ch * 16;
    float l0 = 0.f, l1 = 0.f;
    #pragma unroll
    for (int cc = 0; cc < 16; cc += 4) {
        int c = c0 + cc;
        float4 bv = __ldg((const float4*)(cb1 + c));
        float a0 = bv.x, a1 = bv.y, a2 = bv.z, a3 = bv.w;
        #pragma unroll 8
        for (int k = 0; k < HID; ++k) {
            float xv = xs[k * KF_BBP + bl];
            float4 wv = *(const float4*)(cw1s + k * CH_DIM + c);
            a0 = fmaf(xv, wv.x, a0);
            a1 = fmaf(xv, wv.y, a1);
            a2 = fmaf(xv, wv.z, a2);
            a3 = fmaf(xv, wv.w, a3);
        }
        a0 = fmaxf(a0, 0.f); a1 = fmaxf(a1, 0.f);
        a2 = fmaxf(a2, 0.f); a3 = fmaxf(a3, 0.f);
        float4 wa = __ldg((const float4*)(cw2 + 2 * c));
        float4 wb = __ldg((const float4*)(cw2 + 2 * c + 4));
        l0 += a0 * wa.x + a1 * wa.z + a2 * wb.x + a3 * wb.z;
        l1 += a0 * wa.y + a1 * wa.w + a2 * wb.y + a3 * wb.w;
    }
    pl0[ch * KF_BB + bl] = l0;
    pl1[ch * KF_BB + bl] = l1;
    __syncthreads();
    if (ch == 0) {
        float L0 = 0.f, L1 = 0.f;
        #pragma unroll
        for (int c = 0; c < 8; ++c) { L0 += pl0[c * KF_BB + bl]; L1 += pl1[c * KF_BB + bl]; }
        float m = fmaxf(L0, L1);
        float a0 = expf(L0 - m), a1 = expf(L1 - m);
        float inv = 1.f / (a0 + a1);
        out[(b0 + bl) * 2 + 0] = a0 * inv;
        out[(b0 + bl) * 2 + 1] = a1 * inv;
    }
}

// ---------------- launch (2-stream pipeline, capture-fork pattern) ----------------
extern "C" void kernel_launch(void* const* d_in, const int* in_sizes, int n_in,
                              void* d_out, int out_size) {
    (void)in_sizes; (void)n_in; (void)out_size;
    const float* feats0 = (const float*)d_in[0];
    const float* feats1 = (const float*)d_in[1];
    const float* t0_pw = (const float*)d_in[2];
    const float* t0_pb = (const float*)d_in[3];
    const float* t0_w2 = (const float*)d_in[4];
    const float* t0_b2 = (const float*)d_in[5];
    const float* t0_g  = (const float*)d_in[6];
    const float* t0_be = (const float*)d_in[7];
    const float* t1_pw = (const float*)d_in[8];
    const float* t1_pb = (const float*)d_in[9];
    const float* t1_w2 = (const float*)d_in[10];
    const float* t1_b2 = (const float*)d_in[11];
    const float* t1_g  = (const float*)d_in[12];
    const float* t1_be = (const float*)d_in[13];
    const float* r_vec = (const float*)d_in[14];
    const float* attn_user = (const float*)d_in[15];
    const float* attn_item = (const float*)d_in[16];
    const float* su_w1 = (const float*)d_in[17];
    const float* su_b1 = (const float*)d_in[18];
    const float* su_w2 = (const float*)d_in[19];
    const float* si_w1 = (const float*)d_in[20];
    const float* si_b1 = (const float*)d_in[21];
    const float* si_w2 = (const float*)d_in[22];
    const float* cw1   = (const float*)d_in[23];
    const float* cb1   = (const float*)d_in[24];
    const float* cw2   = (const float*)d_in[25];
    const int* idx0 = (const int*)d_in[26];
    const int* idx1 = (const int*)d_in[27];
    const int* emi_user = (const int*)d_in[28];
    const int* tgt_user = (const int*)d_in[29];
    const int* emi_item = (const int*)d_in[30];
    const int* tgt_item = (const int*)d_in[31];
    float* out = (float*)d_out;

    static cudaStream_t s1 = nullptr;
    static cudaEvent_t evRoot = nullptr, evPre = nullptr, evTow = nullptr, evS1 = nullptr;
    if (!s1) {
        cudaStreamCreateWithFlags(&s1, cudaStreamNonBlocking);
        cudaEventCreateWithFlags(&evRoot, cudaEventDisableTiming);
        cudaEventCreateWithFlags(&evPre,  cudaEventDisableTiming);
        cudaEventCreateWithFlags(&evTow,  cudaEventDisableTiming);
        cudaEventCreateWithFlags(&evS1,   cudaEventDisableTiming);
        cudaFuncSetAttribute(k_tower, cudaFuncAttributeMaxDynamicSharedMemorySize, TOW_SMEM);
        cudaFuncSetAttribute(k_normsem, cudaFuncAttributeMaxDynamicSharedMemorySize, NSEM_SMEM);
        cudaFuncSetAttribute(k_final, cudaFuncAttributeMaxDynamicSharedMemorySize, KF_SMEM);
    }

    void* p_s; void* p_ret; void* p_sem;
    cudaGetSymbolAddress(&p_s, g_s);
    cudaGetSymbolAddress(&p_ret, g_ret);
    cudaGetSymbolAddress(&p_sem, g_sem);

    cudaEventRecord(evRoot, 0);
    cudaStreamWaitEvent(s1, evRoot, 0);

    cudaMemsetAsync(p_s, 0, 4 * BATCH * NHEAD * sizeof(float), s1);
    cudaMemsetAsync(p_ret, 0, (size_t)4 * BATCH * HID * sizeof(float), s1);
    cudaMemsetAsync(p_sem, 0, 4 * sizeof(float), s1);
    k_fr<<<1, 128, 0, s1>>>(r_vec);
    cudaEventRecord(evPre, s1);

    dim3 tg((N0_NODES + TOW_BM - 1) / TOW_BM, 2);
    k_tower<<<tg, 256, TOW_SMEM, 0>>>(feats0, feats1,
        t0_pw, t0_pb, t0_w2, t0_b2, t0_g, t0_be,
        t1_pw, t1_pb, t1_w2, t1_b2, t1_g, t1_be,
        idx0, idx1);

    cudaStreamWaitEvent(0, evPre, 0);
    cudaEventRecord(evTow, 0);
    cudaStreamWaitEvent(s1, evTow, 0);

    const int* emiP[4] = { emi_user, emi_user + (size_t)E_CNT * 3, emi_item, emi_item + (size_t)E_CNT * 3 };
    const int* tgtP[4] = { tgt_user, tgt_user + E_CNT, tgt_item, tgt_item + E_CNT };
    const float* attnP[4] = { attn_user, attn_user + HID, attn_item, attn_item + HID };
    const float* w1P[4] = { su_w1, su_w1, si_w1, si_w1 };
    const float* b1P[4] = { su_b1, su_b1, si_b1, si_b1 };
    const float* w2P[4] = { su_w2, su_w2, si_w2, si_w2 };

    dim3 mg(E_CNT / 32);
    dim3 ng(BATCH / NSEM_BB);
    for (int mp = 0; mp < 4; ++mp) {
        cudaStream_t st = (mp & 1) ? s1 : (cudaStream_t)0;
        k_metapath<<<mg, 256, 0, st>>>(mp, emiP[mp], tgtP[mp], attnP[mp]);
        k_normsem<<<ng, 256, NSEM_SMEM, st>>>(mp, w1P[mp], b1P[mp], w2P[mp]);
    }

    cudaEventRecord(evS1, s1);
    cudaStreamWaitEvent(0, evS1, 0);
    k_final<<<BATCH / KF_BB, 256, KF_SMEM, 0>>>(cw1, cb1, cw2, out);
}

// round 12
// speedup vs baseline: 1.3152x; 1.3152x over previous
#include <cuda_runtime.h>
#include <cuda_bf16.h>
#include <math.h>

// ---------------- problem constants ----------------
#define N0_NODES 20000
#define N_ALL    40000
#define F0_DIM   512
#define HID      64
#define NHEAD    8
#define E_CNT    200000
#define BATCH    8192
#define AV_DIM   128
#define CH_DIM   128

typedef unsigned long long ull;

__device__ __forceinline__ ull pack2(float lo, float hi) {
    ull r; asm("mov.b64 %0, {%1, %2};" : "=l"(r) : "f"(lo), "f"(hi)); return r;
}
__device__ __forceinline__ void unpack2(ull v, float& lo, float& hi) {
    asm("mov.b64 {%0, %1}, %2;" : "=f"(lo), "=f"(hi) : "l"(v));
}
__device__ __forceinline__ void ffma2(ull& d, ull a, ull b) {
    asm("fma.rn.f32x2 %0, %1, %2, %0;" : "+l"(d) : "l"(a), "l"(b));
}
__device__ __forceinline__ ull fadd2(ull a, ull b) {
    ull r; asm("add.rn.f32x2 %0, %1, %2;" : "=l"(r) : "l"(a), "l"(b)); return r;
}
__device__ __forceinline__ float tanh_fast(float x) {
    float y; asm("tanh.approx.f32 %0, %1;" : "=f"(y) : "f"(x)); return y;
}
__device__ __forceinline__ void cpa16(unsigned dst, const float* src, bool valid) {
    int sz = valid ? 16 : 0;
    asm volatile("cp.async.cg.shared.global [%0], [%1], 16, %2;" :: "r"(dst), "l"(src), "r"(sz));
}
#define CP_COMMIT() asm volatile("cp.async.commit_group;")
#define CP_WAIT1()  asm volatile("cp.async.wait_group 1;")
#define CP_WAIT0()  asm volatile("cp.async.wait_group 0;")

// ---------------- device scratch ----------------
__device__ __align__(16) float g_feat[N_ALL * HID];
__device__ __align__(16) float g_fr[4 * 3 * HID];
__device__ __align__(16) float g_s[4 * BATCH * NHEAD];
__device__ __align__(16) float g_ret[4 * BATCH * HID];
__device__ __align__(16) float g_mpout[4 * BATCH * HID];
__device__ __align__(16) float g_sem[4];

// ---------------- rotation precompute ----------------
__global__ void k_fr(const float* __restrict__ r_vec) {
    int tid = threadIdx.x;
    if (tid >= 128) return;
    int mp = tid >> 5, c = tid & 31;
    int et0 = (mp < 2) ? 0 : 1;
    int et1 = (mp < 2) ? 1 : 0;

    float x0 = r_vec[(et1 >> 1) * 64 + 2 * c], y0 = r_vec[(et1 >> 1) * 64 + 2 * c + 1];
    float n = rsqrtf(x0 * x0 + y0 * y0);
    float f1re = x0 * n, f1im = (et1 & 1) ? -y0 * n : y0 * n;

    float x1 = r_vec[(et0 >> 1) * 64 + 2 * c], y1 = r_vec[(et0 >> 1) * 64 + 2 * c + 1];
    n = rsqrtf(x1 * x1 + y1 * y1);
    float r0re = x1 * n, r0im = (et0 & 1) ? -y1 * n : y1 * n;

    float f0re = f1re * r0re - f1im * r0im;
    float f0im = f1re * r0im + f1im * r0re;

    float* base = g_fr + mp * (3 * HID);
    base[0 * HID + 2 * c] = f0re; base[0 * HID + 2 * c + 1] = f0im;
    base[1 * HID + 2 * c] = f1re; base[1 * HID + 2 * c + 1] = f1im;
    base[2 * HID + 2 * c] = 1.f;  base[2 * HID + 2 * c + 1] = 0.f;
}

// ---------------- feature towers (R9 version): cp.async pipelined, f32x2 ----------------
#define TOW_BM   128
#define XS_PITCH 68
#define XS_SZ    (TOW_BM * XS_PITCH)
#define WS_SZ    (64 * 64)
#define TOW_SMEM ((2 * XS_SZ + 2 * WS_SZ) * 4)

__device__ __forceinline__ float gelu_exact(float z) {
    return 0.5f * z * (1.f + erff(z * 0.70710678118654752f));
}

__global__ void __launch_bounds__(256, 2) k_tower(
    const float* __restrict__ f0, const float* __restrict__ f1,
    const float* __restrict__ pw0, const float* __restrict__ pb0,
    const float* __restrict__ w20, const float* __restrict__ b20,
    const float* __restrict__ gm0, const float* __restrict__ be0,
    const float* __restrict__ pw1, const float* __restrict__ pb1,
    const float* __restrict__ w21, const float* __restrict__ b21,
    const float* __restrict__ gm1, const float* __restrict__ be1,
    const int* __restrict__ idx0, const int* __restrict__ idx1)
{
    int t = blockIdx.y;
    const float* feats = t ? f1  : f0;
    const float* pw    = t ? pw1 : pw0;
    const float* pb    = t ? pb1 : pb0;
    const float* w2    = t ? w21 : w20;
    const float* b2    = t ? b21 : b20;
    const float* gmw   = t ? gm1 : gm0;
    const float* bew   = t ? be1 : be0;
    const int*   idx   = t ? idx1 : idx0;

    extern __shared__ float sm[];
    float* xsp[2] = { sm, sm + XS_SZ };
    float* wsp[2] = { sm + 2 * XS_SZ, sm + 2 * XS_SZ + WS_SZ };
    unsigned smem_u32 = (unsigned)__cvta_generic_to_shared(sm);
    unsigned xsa[2] = { smem_u32, smem_u32 + XS_SZ * 4 };
    unsigned wsa[2] = { smem_u32 + 2 * XS_SZ * 4, smem_u32 + (2 * XS_SZ + WS_SZ) * 4 };

    int tid = threadIdx.x;
    int tx = tid & 15, ty = tid >> 4;
    int nb = blockIdx.x * TOW_BM;

    auto prefetch = [&](int kc, int b) {
        #pragma unroll
        for (int r = 0; r < 8; ++r) {
            int i = tid + r * 256;
            int node = i >> 4, kq = i & 15;
            int ng = nb + node;
            cpa16(xsa[b] + (unsigned)(node * XS_PITCH + kq * 4) * 4,
                  feats + (size_t)ng * F0_DIM + kc + kq * 4, ng < N0_NODES);
        }
        #pragma unroll
        for (int r = 0; r < 4; ++r) {
            int i = tid + r * 256;
            int k = i >> 4, cq = i & 15;
            cpa16(wsa[b] + (unsigned)(k * 64 + cq * 4) * 4,
                  pw + (size_t)(kc + k) * HID + cq * 4, true);
        }
        CP_COMMIT();
    };

    float4 pbv = *(const float4*)(pb + tx * 4);
    ull acc[4][4];
    #pragma unroll
    for (int i = 0; i < 4; ++i) {
        acc[i][0] = pack2(pbv.x, pbv.x);
        acc[i][1] = pack2(pbv.y, pbv.y);
        acc[i][2] = pack2(pbv.z, pbv.z);
        acc[i][3] = pack2(pbv.w, pbv.w);
    }

    prefetch(0, 0);

    for (int c = 0; c < 8; ++c) {
        int b = c & 1;
        if (c < 7) { prefetch((c + 1) * 64, b ^ 1); CP_WAIT1(); }
        else       { CP_WAIT0(); }
        __syncthreads();

        const float* xs = xsp[b];
        const float* ws = wsp[b];
        #pragma unroll 4
        for (int k = 0; k < 64; ++k) {
            float4 wv = *(const float4*)(ws + k * 64 + tx * 4);
            ull w0 = pack2(wv.x, wv.x), w1 = pack2(wv.y, wv.y);
            ull w2p = pack2(wv.z, wv.z), w3 = pack2(wv.w, wv.w);
            #pragma unroll
            for (int i = 0; i < 4; ++i) {
                int row = ty * 8 + 2 * i;
                ull xv = pack2(xs[row * XS_PITCH + k], xs[(row + 1) * XS_PITCH + k]);
                ffma2(acc[i][0], xv, w0);
                ffma2(acc[i][1], xv, w1);
                ffma2(acc[i][2], xv, w2p);
                ffma2(acc[i][3], xv, w3);
            }
        }
        __syncthreads();
    }

    #pragma unroll
    for (int r = 0; r < 4; ++r) {
        int i = tid + r * 256;
        int k = i >> 4, cq = i & 15;
        cpa16(wsa[0] + (unsigned)(k * 64 + cq * 4) * 4, w2 + (size_t)k * HID + cq * 4, true);
    }
    CP_COMMIT();

    #pragma unroll
    for (int i = 0; i < 4; ++i)
        #pragma unroll
        for (int j = 0; j < 4; ++j) {
            float zl, zh;
            unpack2(acc[i][j], zl, zh);
            int row = ty * 8 + 2 * i, col = tx * 4 + j;
            xsp[0][row * XS_PITCH + col] = gelu_exact(zl);
            xsp[0][(row + 1) * XS_PITCH + col] = gelu_exact(zh);
        }
    CP_WAIT0();
    __syncthreads();

    float4 b2v = *(const float4*)(b2 + tx * 4);
    ull yacc[4][4];
    #pragma unroll
    for (int i = 0; i < 4; ++i) {
        yacc[i][0] = fadd2(acc[i][0], pack2(b2v.x, b2v.x));
        yacc[i][1] = fadd2(acc[i][1], pack2(b2v.y, b2v.y));
        yacc[i][2] = fadd2(acc[i][2], pack2(b2v.z, b2v.z));
        yacc[i][3] = fadd2(acc[i][3], pack2(b2v.w, b2v.w));
    }
    {
        const float* xs = xsp[0];
        const float* ws = wsp[0];
        #pragma unroll 4
        for (int k = 0; k < 64; ++k) {
            float4 wv = *(const float4*)(ws + k * 64 + tx * 4);
            ull w0 = pack2(wv.x, wv.x), w1 = pack2(wv.y, wv.y);
            ull w2p = pack2(wv.z, wv.z), w3 = pack2(wv.w, wv.w);
            #pragma unroll
            for (int i = 0; i < 4; ++i) {
                int row = ty * 8 + 2 * i;
                ull xv = pack2(xs[row * XS_PITCH + k], xs[(row + 1) * XS_PITCH + k]);
                ffma2(yacc[i][0], xv, w0);
                ffma2(yacc[i][1], xv, w1);
                ffma2(yacc[i][2], xv, w2p);
                ffma2(yacc[i][3], xv, w3);
            }
        }
    }

    float y[8][4];
    #pragma unroll
    for (int i = 0; i < 4; ++i)
        #pragma unroll
        for (int j = 0; j < 4; ++j)
            unpack2(yacc[i][j], y[2 * i][j], y[2 * i + 1][j]);

    float4 gv = *(const float4*)(gmw + tx * 4);
    float4 bev = *(const float4*)(bew + tx * 4);

    #pragma unroll
    for (int i = 0; i < 8; ++i) {
        float s1 = y[i][0] + y[i][1] + y[i][2] + y[i][3];
        float s2 = y[i][0] * y[i][0] + y[i][1] * y[i][1] + y[i][2] * y[i][2] + y[i][3] * y[i][3];
        #pragma unroll
        for (int o = 8; o > 0; o >>= 1) {
            s1 += __shfl_xor_sync(0xffffffffu, s1, o);
            s2 += __shfl_xor_sync(0xffffffffu, s2, o);
        }
        float mu  = s1 * (1.f / 64.f);
        float var = s2 * (1.f / 64.f) - mu * mu;
        float rs  = rsqrtf(var + 1e-5f);
        int ng = nb + ty * 8 + i;
        if (ng < N0_NODES) {
            int dst = idx[ng];
            float4 o4;
            o4.x = (y[i][0] - mu) * rs * gv.x + bev.x;
            o4.y = (y[i][1] - mu) * rs * gv.y + bev.y;
            o4.z = (y[i][2] - mu) * rs * gv.z + bev.z;
            o4.w = (y[i][3] - mu) * rs * gv.w + bev.w;
            *(float4*)(g_feat + (size_t)dst * HID + tx * 4) = o4;
        }
    }
}

// ---------------- metapath gather (per-mp launch): 2 instances per thread ----------------
__global__ void k_metapath(
    int mp,
    const int* __restrict__ emi, const int* __restrict__ tgt,
    const float* __restrict__ attn)
{
    int tid  = threadIdx.x;
    int sub  = tid & 15;
    int instA = blockIdx.x * 16 + (tid >> 4);
    int instB = instA + E_CNT / 2;

    const float4* fr4 = (const float4*)g_fr + mp * 48;
    float4 fr0 = fr4[sub], fr1 = fr4[16 + sub], fr2 = fr4[32 + sub];
    float4 av = ((const float4*)attn)[sub];

    int a0 = __ldg(emi + instA * 3);
    int a1 = __ldg(emi + instA * 3 + 1);
    int a2 = __ldg(emi + instA * 3 + 2);
    int b0i = __ldg(emi + instB * 3);
    int b1i = __ldg(emi + instB * 3 + 1);
    int b2i = __ldg(emi + instB * 3 + 2);
    int tA = __ldg(tgt + instA);
    int tB = __ldg(tgt + instB);

    const float4* feat4 = (const float4*)g_feat;
    float4 vA0 = __ldg(feat4 + (size_t)a0 * 16 + sub);
    float4 vA1 = __ldg(feat4 + (size_t)a1 * 16 + sub);
    float4 vA2 = __ldg(feat4 + (size_t)a2 * 16 + sub);
    float4 vB0 = __ldg(feat4 + (size_t)b0i * 16 + sub);
    float4 vB1 = __ldg(feat4 + (size_t)b1i * 16 + sub);
    float4 vB2 = __ldg(feat4 + (size_t)b2i * 16 + sub);

    const float inv3 = (1.f / 3.f);

    {
        float hx = (vA0.x * fr0.x - vA0.y * fr0.y) + (vA1.x * fr1.x - vA1.y * fr1.y) + (vA2.x * fr2.x - vA2.y * fr2.y);
        float hy = (vA0.x * fr0.y + vA0.y * fr0.x) + (vA1.x * fr1.y + vA1.y * fr1.x) + (vA2.x * fr2.y + vA2.y * fr2.x);
        float hz = (vA0.z * fr0.z - vA0.w * fr0.w) + (vA1.z * fr1.z - vA1.w * fr1.w) + (vA2.z * fr2.z - vA2.w * fr2.w);
        float hw = (vA0.z * fr0.w + vA0.w * fr0.z) + (vA1.z * fr1.w + vA1.w * fr1.z) + (vA2.z * fr2.w + vA2.w * fr2.z);
        hx *= inv3; hy *= inv3; hz *= inv3; hw *= inv3;

        float p = hx * av.x + hy * av.y + hz * av.z + hw * av.w;
        p += __shfl_xor_sync(0xffffffffu, p, 1);
        float e = p > 0.f ? p : 0.01f * p;
        float a = expf(e);

        size_t base = (size_t)mp * BATCH + tA;
        if (!(sub & 1)) atomicAdd(&g_s[base * NHEAD + (sub >> 1)], a);
        float* rb = g_ret + base * HID + sub * 4;
        asm volatile("red.global.add.v4.f32 [%0], {%1, %2, %3, %4};"
                     :: "l"(rb), "f"(a * hx), "f"(a * hy), "f"(a * hz), "f"(a * hw)
                     : "memory");
    }
    {
        float hx = (vB0.x * fr0.x - vB0.y * fr0.y) + (vB1.x * fr1.x - vB1.y * fr1.y) + (vB2.x * fr2.x - vB2.y * fr2.y);
        float hy = (vB0.x * fr0.y + vB0.y * fr0.x) + (vB1.x * fr1.y + vB1.y * fr1.x) + (vB2.x * fr2.y + vB2.y * fr2.x);
        float hz = (vB0.z * fr0.z - vB0.w * fr0.w) + (vB1.z * fr1.z - vB1.w * fr1.w) + (vB2.z * fr2.z - vB2.w * fr2.w);
        float hw = (vB0.z * fr0.w + vB0.w * fr0.z) + (vB1.z * fr1.w + vB1.w * fr1.z) + (vB2.z * fr2.w + vB2.w * fr2.z);
        hx *= inv3; hy *= inv3; hz *= inv3; hw *= inv3;

        float p = hx * av.x + hy * av.y + hz * av.z + hw * av.w;
        p += __shfl_xor_sync(0xffffffffu, p, 1);
        float e = p > 0.f ? p : 0.01f * p;
        float a = expf(e);

        size_t base = (size_t)mp * BATCH + tB;
        if (!(sub & 1)) atomicAdd(&g_s[base * NHEAD + (sub >> 1)], a);
        float* rb = g_ret + base * HID + sub * 4;
        asm volatile("red.global.add.v4.f32 [%0], {%1, %2, %3, %4};"
                     :: "l"(rb), "f"(a * hx), "f"(a * hy), "f"(a * hz), "f"(a * hw)
                     : "memory");
    }
}

// ---------------- fused normalize+elu+mpout + semantic GEMV ----------------
// per-mp. grid BATCH/16 = 512 blocks, block 256. w1 via L1-broadcast __ldg (no smem).
// Thread: bl = tid&15 (row), ch = tid>>4 (8-col chunk). Full block reduce -> g_sem.
#define NSEM_BB  16
#define NSEM_BBP 17
__global__ void __launch_bounds__(256) k_normsem(
    int mp,
    const float* __restrict__ w1, const float* __restrict__ b1, const float* __restrict__ w2)
{
    __shared__ float hs[HID * NSEM_BBP];   // 4.4KB
    __shared__ float rbuf[8];
    int tid = threadIdx.x;
    int b0 = blockIdx.x * NSEM_BB;

    #pragma unroll
    for (int r = 0; r < 4; ++r) {
        int i = tid + r * 256;
        int bl = i >> 6, k = i & 63;
        size_t row = (size_t)mp * BATCH + b0 + bl;
        float sv = g_s[row * NHEAD + (k >> 3)];
        float v = g_ret[row * HID + k] / (sv + 1e-9f);
        v = v > 0.f ? v : expf(v) - 1.f;
        g_mpout[row * HID + k] = v;
        hs[k * NSEM_BBP + bl] = v;
    }
    __syncthreads();

    int bl = tid & 15, ch = tid >> 4;
    int c0 = ch * 8;
    ull acc[4];
    {
        float4 ba = __ldg((const float4*)(b1 + c0));
        float4 bb = __ldg((const float4*)(b1 + c0 + 4));
        acc[0] = pack2(ba.x, ba.y); acc[1] = pack2(ba.z, ba.w);
        acc[2] = pack2(bb.x, bb.y); acc[3] = pack2(bb.z, bb.w);
    }
    #pragma unroll 8
    for (int k = 0; k < HID; ++k) {
        float xv = hs[k * NSEM_BBP + bl];
        ull xp = pack2(xv, xv);
        float4 wa = __ldg((const float4*)(w1 + k * AV_DIM + c0));
        float4 wb = __ldg((const float4*)(w1 + k * AV_DIM + c0 + 4));
        ffma2(acc[0], xp, pack2(wa.x, wa.y));
        ffma2(acc[1], xp, pack2(wa.z, wa.w));
        ffma2(acc[2], xp, pack2(wb.x, wb.y));
        ffma2(acc[3], xp, pack2(wb.z, wb.w));
    }
    float ssum = 0.f;
    {
        float4 wa = __ldg((const float4*)(w2 + c0));
        float4 wb = __ldg((const float4*)(w2 + c0 + 4));
        float lo, hi;
        unpack2(acc[0], lo, hi); ssum += tanh_fast(lo) * wa.x + tanh_fast(hi) * wa.y;
        unpack2(acc[1], lo, hi); ssum += tanh_fast(lo) * wa.z + tanh_fast(hi) * wa.w;
        unpack2(acc[2], lo, hi); ssum += tanh_fast(lo) * wb.x + tanh_fast(hi) * wb.y;
        unpack2(acc[3], lo, hi); ssum += tanh_fast(lo) * wb.z + tanh_fast(hi) * wb.w;
    }
    #pragma unroll
    for (int o = 16; o > 0; o >>= 1) ssum += __shfl_xor_sync(0xffffffffu, ssum, o);
    if ((tid & 31) == 0) rbuf[tid >> 5] = ssum;
    __syncthreads();
    if (tid == 0) {
        float t = rbuf[0] + rbuf[1] + rbuf[2] + rbuf[3] + rbuf[4] + rbuf[5] + rbuf[6] + rbuf[7];
        atomicAdd(&g_sem[mp], t);
    }
}

// ---------------- semantic fusion + product MLP + softmax ----------------
// grid BATCH/16 = 512 blocks, block 256. cw1 via L1-broadcast __ldg.
// Thread: bl = tid&15, ch = tid>>4 (8 cols). Per-row reduce via shfl + smem.
#define KF_BB  16
#define KF_BBP 17
__global__ void __launch_bounds__(256) k_final(
    const float* __restrict__ cw1, const float* __restrict__ cb1,
    const float* __restrict__ cw2, float* __restrict__ out)
{
    __shared__ float xs[HID * KF_BBP];     // 4.4KB
    __shared__ float pr0[8][KF_BB], pr1[8][KF_BB];
    int tid = threadIdx.x;
    int b0 = blockIdx.x * KF_BB;

    float s0 = g_sem[0] * (1.f / BATCH), s1 = g_sem[1] * (1.f / BATCH);
    float s2 = g_sem[2] * (1.f / BATCH), s3 = g_sem[3] * (1.f / BATCH);
    float mU = fmaxf(s0, s1), mI = fmaxf(s2, s3);
    float e0 = expf(s0 - mU), e1 = expf(s1 - mU);
    float e2 = expf(s2 - mI), e3 = expf(s3 - mI);
    float bu0 = e0 / (e0 + e1), bu1 = e1 / (e0 + e1);
    float bi0 = e2 / (e2 + e3), bi1 = e3 / (e2 + e3);

    #pragma unroll
    for (int r = 0; r < 4; ++r) {
        int i = tid + r * 256;
        int bl = i >> 6, k = i & 63;
        size_t b = b0 + bl;
        float hu = bu0 * g_mpout[((size_t)0 * BATCH + b) * HID + k]
                 + bu1 * g_mpout[((size_t)1 * BATCH + b) * HID + k];
        float hi = bi0 * g_mpout[((size_t)2 * BATCH + b) * HID + k]
                 + bi1 * g_mpout[((size_t)3 * BATCH + b) * HID + k];
        xs[k * KF_BBP + bl] = hu * hi;
    }
    __syncthreads();

    int bl = tid & 15, ch = tid >> 4;
    int c0 = ch * 8;
    float a0, a1, a2, a3, a4, a5, a6, a7;
    {
        float4 ba = __ldg((const float4*)(cb1 + c0));
        float4 bb = __ldg((const float4*)(cb1 + c0 + 4));
        a0 = ba.x; a1 = ba.y; a2 = ba.z; a3 = ba.w;
        a4 = bb.x; a5 = bb.y; a6 = bb.z; a7 = bb.w;
    }
    #pragma unroll 8
    for (int k = 0; k < HID; ++k) {
        float xv = xs[k * KF_BBP + bl];
        float4 wa = __ldg((const float4*)(cw1 + k * CH_DIM + c0));
        float4 wb = __ldg((const float4*)(cw1 + k * CH_DIM + c0 + 4));
        a0 = fmaf(xv, wa.x, a0); a1 = fmaf(xv, wa.y, a1);
        a2 = fmaf(xv, wa.z, a2); a3 = fmaf(xv, wa.w, a3);
        a4 = fmaf(xv, wb.x, a4); a5 = fmaf(xv, wb.y, a5);
        a6 = fmaf(xv, wb.z, a6); a7 = fmaf(xv, wb.w, a7);
    }
    a0 = fmaxf(a0, 0.f); a1 = fmaxf(a1, 0.f); a2 = fmaxf(a2, 0.f); a3 = fmaxf(a3, 0.f);
    a4 = fmaxf(a4, 0.f); a5 = fmaxf(a5, 0.f); a6 = fmaxf(a6, 0.f); a7 = fmaxf(a7, 0.f);

    float l0, l1;
    {
        float4 wA = __ldg((const float4*)(cw2 + 2 * c0));       // cols c0, c0+1
        float4 wB = __ldg((const float4*)(cw2 + 2 * c0 + 4));   // c0+2, c0+3
        float4 wC = __ldg((const float4*)(cw2 + 2 * c0 + 8));   // c0+4, c0+5
        float4 wD = __ldg((const float4*)(cw2 + 2 * c0 + 12));  // c0+6, c0+7
        l0 = a0 * wA.x + a1 * wA.z + a2 * wB.x + a3 * wB.z
           + a4 * wC.x + a5 * wC.z + a6 * wD.x + a7 * wD.z;
        l1 = a0 * wA.y + a1 * wA.w + a2 * wB.y + a3 * wB.w
           + a4 * wC.y + a5 * wC.w + a6 * wD.y + a7 * wD.w;
    }
    // combine the two ch chunks within this warp (lanes bl and bl+16 share row)
    l0 += __shfl_xor_sync(0xffffffffu, l0, 16);
    l1 += __shfl_xor_sync(0xffffffffu, l1, 16);
    int warp = tid >> 5;
    if ((tid & 31) < 16) { pr0[warp][bl] = l0; pr1[warp][bl] = l1; }
    __syncthreads();
    if (tid < KF_BB) {
        float L0 = 0.f, L1 = 0.f;
        #pragma unroll
        for (int w = 0; w < 8; ++w) { L0 += pr0[w][tid]; L1 += pr1[w][tid]; }
        float m = fmaxf(L0, L1);
        float q0 = expf(L0 - m), q1 = expf(L1 - m);
        float inv = 1.f / (q0 + q1);
        out[(b0 + tid) * 2 + 0] = q0 * inv;
        out[(b0 + tid) * 2 + 1] = q1 * inv;
    }
}

// ---------------- launch (2-stream pipeline, capture-fork pattern) ----------------
extern "C" void kernel_launch(void* const* d_in, const int* in_sizes, int n_in,
                              void* d_out, int out_size) {
    (void)in_sizes; (void)n_in; (void)out_size;
    const float* feats0 = (const float*)d_in[0];
    const float* feats1 = (const float*)d_in[1];
    const float* t0_pw = (const float*)d_in[2];
    const float* t0_pb = (const float*)d_in[3];
    const float* t0_w2 = (const float*)d_in[4];
    const float* t0_b2 = (const float*)d_in[5];
    const float* t0_g  = (const float*)d_in[6];
    const float* t0_be = (const float*)d_in[7];
    const float* t1_pw = (const float*)d_in[8];
    const float* t1_pb = (const float*)d_in[9];
    const float* t1_w2 = (const float*)d_in[10];
    const float* t1_b2 = (const float*)d_in[11];
    const float* t1_g  = (const float*)d_in[12];
    const float* t1_be = (const float*)d_in[13];
    const float* r_vec = (const float*)d_in[14];
    const float* attn_user = (const float*)d_in[15];
    const float* attn_item = (const float*)d_in[16];
    const float* su_w1 = (const float*)d_in[17];
    const float* su_b1 = (const float*)d_in[18];
    const float* su_w2 = (const float*)d_in[19];
    const float* si_w1 = (const float*)d_in[20];
    const float* si_b1 = (const float*)d_in[21];
    const float* si_w2 = (const float*)d_in[22];
    const float* cw1   = (const float*)d_in[23];
    const float* cb1   = (const float*)d_in[24];
    const float* cw2   = (const float*)d_in[25];
    const int* idx0 = (const int*)d_in[26];
    const int* idx1 = (const int*)d_in[27];
    const int* emi_user = (const int*)d_in[28];
    const int* tgt_user = (const int*)d_in[29];
    const int* emi_item = (const int*)d_in[30];
    const int* tgt_item = (const int*)d_in[31];
    float* out = (float*)d_out;

    static cudaStream_t s1 = nullptr;
    static cudaEvent_t evRoot = nullptr, evPre = nullptr, evTow = nullptr, evS1 = nullptr;
    if (!s1) {
        cudaStreamCreateWithFlags(&s1, cudaStreamNonBlocking);
        cudaEventCreateWithFlags(&evRoot, cudaEventDisableTiming);
        cudaEventCreateWithFlags(&evPre,  cudaEventDisableTiming);
        cudaEventCreateWithFlags(&evTow,  cudaEventDisableTiming);
        cudaEventCreateWithFlags(&evS1,   cudaEventDisableTiming);
        cudaFuncSetAttribute(k_tower, cudaFuncAttributeMaxDynamicSharedMemorySize, TOW_SMEM);
    }

    void* p_s; void* p_ret; void* p_sem;
    cudaGetSymbolAddress(&p_s, g_s);
    cudaGetSymbolAddress(&p_ret, g_ret);
    cudaGetSymbolAddress(&p_sem, g_sem);

    cudaEventRecord(evRoot, 0);
    cudaStreamWaitEvent(s1, evRoot, 0);

    cudaMemsetAsync(p_s, 0, 4 * BATCH * NHEAD * sizeof(float), s1);
    cudaMemsetAsync(p_ret, 0, (size_t)4 * BATCH * HID * sizeof(float), s1);
    cudaMemsetAsync(p_sem, 0, 4 * sizeof(float), s1);
    k_fr<<<1, 128, 0, s1>>>(r_vec);
    cudaEventRecord(evPre, s1);

    dim3 tg((N0_NODES + TOW_BM - 1) / TOW_BM, 2);
    k_tower<<<tg, 256, TOW_SMEM, 0>>>(feats0, feats1,
        t0_pw, t0_pb, t0_w2, t0_b2, t0_g, t0_be,
        t1_pw, t1_pb, t1_w2, t1_b2, t1_g, t1_be,
        idx0, idx1);

    cudaStreamWaitEvent(0, evPre, 0);
    cudaEventRecord(evTow, 0);
    cudaStreamWaitEvent(s1, evTow, 0);

    const int* emiP[4] = { emi_user, emi_user + (size_t)E_CNT * 3, emi_item, emi_item + (size_t)E_CNT * 3 };
    const int* tgtP[4] = { tgt_user, tgt_user + E_CNT, tgt_item, tgt_item + E_CNT };
    const float* attnP[4] = { attn_user, attn_user + HID, attn_item, attn_item + HID };
    const float* w1P[4] = { su_w1, su_w1, si_w1, si_w1 };
    const float* b1P[4] = { su_b1, su_b1, si_b1, si_b1 };
    const float* w2P[4] = { su_w2, su_w2, si_w2, si_w2 };

    dim3 mg(E_CNT / 32);
    dim3 ng(BATCH / NSEM_BB);
    for (int mp = 0; mp < 4; ++mp) {
        cudaStream_t st = (mp & 1) ? s1 : (cudaStream_t)0;
        k_metapath<<<mg, 256, 0, st>>>(mp, emiP[mp], tgtP[mp], attnP[mp]);
        k_normsem<<<ng, 256, 0, st>>>(mp, w1P[mp], b1P[mp], w2P[mp]);
    }

    cudaEventRecord(evS1, s1);
    cudaStreamWaitEvent(0, evS1, 0);
    k_final<<<BATCH / KF_BB, 256, 0, 0>>>(cw1, cb1, cw2, out);
}

// round 14
// speedup vs baseline: 1.4310x; 1.0881x over previous
#include <cuda_runtime.h>
#include <cuda_bf16.h>
#include <cuda_fp16.h>
#include <math.h>

// ---------------- problem constants ----------------
#define N0_NODES 20000
#define N_ALL    40000
#define F0_DIM   512
#define HID      64
#define NHEAD    8
#define E_CNT    200000
#define BATCH    8192
#define AV_DIM   128
#define CH_DIM   128

typedef unsigned long long ull;

__device__ __forceinline__ ull pack2(float lo, float hi) {
    ull r; asm("mov.b64 %0, {%1, %2};" : "=l"(r) : "f"(lo), "f"(hi)); return r;
}
__device__ __forceinline__ void unpack2(ull v, float& lo, float& hi) {
    asm("mov.b64 {%0, %1}, %2;" : "=f"(lo), "=f"(hi) : "l"(v));
}
__device__ __forceinline__ void ffma2(ull& d, ull a, ull b) {
    asm("fma.rn.f32x2 %0, %1, %2, %0;" : "+l"(d) : "l"(a), "l"(b));
}
__device__ __forceinline__ ull fadd2(ull a, ull b) {
    ull r; asm("add.rn.f32x2 %0, %1, %2;" : "=l"(r) : "l"(a), "l"(b)); return r;
}
__device__ __forceinline__ float tanh_fast(float x) {
    float y; asm("tanh.approx.f32 %0, %1;" : "=f"(y) : "f"(x)); return y;
}
__device__ __forceinline__ void cpa16(unsigned dst, const float* src, bool valid) {
    int sz = valid ? 16 : 0;
    asm volatile("cp.async.cg.shared.global [%0], [%1], 16, %2;" :: "r"(dst), "l"(src), "r"(sz));
}
#define CP_COMMIT() asm volatile("cp.async.commit_group;")
#define CP_WAIT1()  asm volatile("cp.async.wait_group 1;")
#define CP_WAIT0()  asm volatile("cp.async.wait_group 0;")

// ---------------- device scratch ----------------
__device__ __align__(16) __half g_feat_h[N_ALL * HID];   // fp16 feature table, 5.1MB
__device__ __align__(16) float g_fr[4 * 3 * HID];
__device__ __align__(16) float g_s[4 * BATCH * NHEAD];
__device__ __align__(16) float g_ret[4 * BATCH * HID];
__device__ __align__(16) float g_mpout[4 * BATCH * HID];
__device__ __align__(16) float g_sem[4];

// ---------------- rotation precompute ----------------
__global__ void k_fr(const float* __restrict__ r_vec) {
    int tid = threadIdx.x;
    if (tid >= 128) return;
    int mp = tid >> 5, c = tid & 31;
    int et0 = (mp < 2) ? 0 : 1;
    int et1 = (mp < 2) ? 1 : 0;

    float x0 = r_vec[(et1 >> 1) * 64 + 2 * c], y0 = r_vec[(et1 >> 1) * 64 + 2 * c + 1];
    float n = rsqrtf(x0 * x0 + y0 * y0);
    float f1re = x0 * n, f1im = (et1 & 1) ? -y0 * n : y0 * n;

    float x1 = r_vec[(et0 >> 1) * 64 + 2 * c], y1 = r_vec[(et0 >> 1) * 64 + 2 * c + 1];
    n = rsqrtf(x1 * x1 + y1 * y1);
    float r0re = x1 * n, r0im = (et0 & 1) ? -y1 * n : y1 * n;

    float f0re = f1re * r0re - f1im * r0im;
    float f0im = f1re * r0im + f1im * r0re;

    float* base = g_fr + mp * (3 * HID);
    base[0 * HID + 2 * c] = f0re; base[0 * HID + 2 * c + 1] = f0im;
    base[1 * HID + 2 * c] = f1re; base[1 * HID + 2 * c + 1] = f1im;
    base[2 * HID + 2 * c] = 1.f;  base[2 * HID + 2 * c + 1] = 0.f;
}

// ---------------- feature towers (R9): cp.async pipelined, f32x2; fp16 store ----------------
#define TOW_BM   128
#define XS_PITCH 68
#define XS_SZ    (TOW_BM * XS_PITCH)
#define WS_SZ    (64 * 64)
#define TOW_SMEM ((2 * XS_SZ + 2 * WS_SZ) * 4)

__device__ __forceinline__ float gelu_exact(float z) {
    return 0.5f * z * (1.f + erff(z * 0.70710678118654752f));
}

__global__ void __launch_bounds__(256, 2) k_tower(
    const float* __restrict__ f0, const float* __restrict__ f1,
    const float* __restrict__ pw0, const float* __restrict__ pb0,
    const float* __restrict__ w20, const float* __restrict__ b20,
    const float* __restrict__ gm0, const float* __restrict__ be0,
    const float* __restrict__ pw1, const float* __restrict__ pb1,
    const float* __restrict__ w21, const float* __restrict__ b21,
    const float* __restrict__ gm1, const float* __restrict__ be1,
    const int* __restrict__ idx0, const int* __restrict__ idx1)
{
    int t = blockIdx.y;
    const float* feats = t ? f1  : f0;
    const float* pw    = t ? pw1 : pw0;
    const float* pb    = t ? pb1 : pb0;
    const float* w2    = t ? w21 : w20;
    const float* b2    = t ? b21 : b20;
    const float* gmw   = t ? gm1 : gm0;
    const float* bew   = t ? be1 : be0;
    const int*   idx   = t ? idx1 : idx0;

    extern __shared__ float sm[];
    float* xsp[2] = { sm, sm + XS_SZ };
    float* wsp[2] = { sm + 2 * XS_SZ, sm + 2 * XS_SZ + WS_SZ };
    unsigned smem_u32 = (unsigned)__cvta_generic_to_shared(sm);
    unsigned xsa[2] = { smem_u32, smem_u32 + XS_SZ * 4 };
    unsigned wsa[2] = { smem_u32 + 2 * XS_SZ * 4, smem_u32 + (2 * XS_SZ + WS_SZ) * 4 };

    int tid = threadIdx.x;
    int tx = tid & 15, ty = tid >> 4;
    int nb = blockIdx.x * TOW_BM;

    auto prefetch = [&](int kc, int b) {
        #pragma unroll
        for (int r = 0; r < 8; ++r) {
            int i = tid + r * 256;
            int node = i >> 4, kq = i & 15;
            int ng = nb + node;
            cpa16(xsa[b] + (unsigned)(node * XS_PITCH + kq * 4) * 4,
                  feats + (size_t)ng * F0_DIM + kc + kq * 4, ng < N0_NODES);
        }
        #pragma unroll
        for (int r = 0; r < 4; ++r) {
            int i = tid + r * 256;
            int k = i >> 4, cq = i & 15;
            cpa16(wsa[b] + (unsigned)(k * 64 + cq * 4) * 4,
                  pw + (size_t)(kc + k) * HID + cq * 4, true);
        }
        CP_COMMIT();
    };

    float4 pbv = *(const float4*)(pb + tx * 4);
    ull acc[4][4];
    #pragma unroll
    for (int i = 0; i < 4; ++i) {
        acc[i][0] = pack2(pbv.x, pbv.x);
        acc[i][1] = pack2(pbv.y, pbv.y);
        acc[i][2] = pack2(pbv.z, pbv.z);
        acc[i][3] = pack2(pbv.w, pbv.w);
    }

    prefetch(0, 0);

    for (int c = 0; c < 8; ++c) {
        int b = c & 1;
        if (c < 7) { prefetch((c + 1) * 64, b ^ 1); CP_WAIT1(); }
        else       { CP_WAIT0(); }
        __syncthreads();

        const float* xs = xsp[b];
        const float* ws = wsp[b];
        #pragma unroll 4
        for (int k = 0; k < 64; ++k) {
            float4 wv = *(const float4*)(ws + k * 64 + tx * 4);
            ull w0 = pack2(wv.x, wv.x), w1 = pack2(wv.y, wv.y);
            ull w2p = pack2(wv.z, wv.z), w3 = pack2(wv.w, wv.w);
            #pragma unroll
            for (int i = 0; i < 4; ++i) {
                int row = ty * 8 + 2 * i;
                ull xv = pack2(xs[row * XS_PITCH + k], xs[(row + 1) * XS_PITCH + k]);
                ffma2(acc[i][0], xv, w0);
                ffma2(acc[i][1], xv, w1);
                ffma2(acc[i][2], xv, w2p);
                ffma2(acc[i][3], xv, w3);
            }
        }
        __syncthreads();
    }

    #pragma unroll
    for (int r = 0; r < 4; ++r) {
        int i = tid + r * 256;
        int k = i >> 4, cq = i & 15;
        cpa16(wsa[0] + (unsigned)(k * 64 + cq * 4) * 4, w2 + (size_t)k * HID + cq * 4, true);
    }
    CP_COMMIT();

    #pragma unroll
    for (int i = 0; i < 4; ++i)
        #pragma unroll
        for (int j = 0; j < 4; ++j) {
            float zl, zh;
            unpack2(acc[i][j], zl, zh);
            int row = ty * 8 + 2 * i, col = tx * 4 + j;
            xsp[0][row * XS_PITCH + col] = gelu_exact(zl);
            xsp[0][(row + 1) * XS_PITCH + col] = gelu_exact(zh);
        }
    CP_WAIT0();
    __syncthreads();

    float4 b2v = *(const float4*)(b2 + tx * 4);
    ull yacc[4][4];
    #pragma unroll
    for (int i = 0; i < 4; ++i) {
        yacc[i][0] = fadd2(acc[i][0], pack2(b2v.x, b2v.x));
        yacc[i][1] = fadd2(acc[i][1], pack2(b2v.y, b2v.y));
        yacc[i][2] = fadd2(acc[i][2], pack2(b2v.z, b2v.z));
        yacc[i][3] = fadd2(acc[i][3], pack2(b2v.w, b2v.w));
    }
    {
        const float* xs = xsp[0];
        const float* ws = wsp[0];
        #pragma unroll 4
        for (int k = 0; k < 64; ++k) {
            float4 wv = *(const float4*)(ws + k * 64 + tx * 4);
            ull w0 = pack2(wv.x, wv.x), w1 = pack2(wv.y, wv.y);
            ull w2p = pack2(wv.z, wv.z), w3 = pack2(wv.w, wv.w);
            #pragma unroll
            for (int i = 0; i < 4; ++i) {
                int row = ty * 8 + 2 * i;
                ull xv = pack2(xs[row * XS_PITCH + k], xs[(row + 1) * XS_PITCH + k]);
                ffma2(yacc[i][0], xv, w0);
                ffma2(yacc[i][1], xv, w1);
                ffma2(yacc[i][2], xv, w2p);
                ffma2(yacc[i][3], xv, w3);
            }
        }
    }

    float y[8][4];
    #pragma unroll
    for (int i = 0; i < 4; ++i)
        #pragma unroll
        for (int j = 0; j < 4; ++j)
            unpack2(yacc[i][j], y[2 * i][j], y[2 * i + 1][j]);

    float4 gv = *(const float4*)(gmw + tx * 4);
    float4 bev = *(const float4*)(bew + tx * 4);

    #pragma unroll
    for (int i = 0; i < 8; ++i) {
        float s1 = y[i][0] + y[i][1] + y[i][2] + y[i][3];
        float s2 = y[i][0] * y[i][0] + y[i][1] * y[i][1] + y[i][2] * y[i][2] + y[i][3] * y[i][3];
        #pragma unroll
        for (int o = 8; o > 0; o >>= 1) {
            s1 += __shfl_xor_sync(0xffffffffu, s1, o);
            s2 += __shfl_xor_sync(0xffffffffu, s2, o);
        }
        float mu  = s1 * (1.f / 64.f);
        float var = s2 * (1.f / 64.f) - mu * mu;
        float rs  = rsqrtf(var + 1e-5f);
        int ng = nb + ty * 8 + i;
        if (ng < N0_NODES) {
            int dst = idx[ng];
            __half2 p0 = __floats2half2_rn((y[i][0] - mu) * rs * gv.x + bev.x,
                                           (y[i][1] - mu) * rs * gv.y + bev.y);
            __half2 p1 = __floats2half2_rn((y[i][2] - mu) * rs * gv.z + bev.z,
                                           (y[i][3] - mu) * rs * gv.w + bev.w);
            uint2 st;
            st.x = *(unsigned*)&p0;
            st.y = *(unsigned*)&p1;
            *(uint2*)(g_feat_h + (size_t)dst * HID + tx * 4) = st;
        }
    }
}

// ---------------- metapath gather (per-mp): 2 instances/thread, fp16 table ----------------
__device__ __forceinline__ float4 ldg_feat_h(const uint2* feat2, size_t off) {
    uint2 r = __ldg(feat2 + off);
    __half2 h0 = *(__half2*)&r.x;
    __half2 h1 = *(__half2*)&r.y;
    float2 lo = __half22float2(h0);
    float2 hi = __half22float2(h1);
    return make_float4(lo.x, lo.y, hi.x, hi.y);
}

__global__ void k_metapath(
    int mp,
    const int* __restrict__ emi, const int* __restrict__ tgt,
    const float* __restrict__ attn)
{
    int tid  = threadIdx.x;
    int sub  = tid & 15;
    int instA = blockIdx.x * 16 + (tid >> 4);
    int instB = instA + E_CNT / 2;

    const float4* fr4 = (const float4*)g_fr + mp * 48;
    float4 fr0 = fr4[sub], fr1 = fr4[16 + sub], fr2 = fr4[32 + sub];
    float4 av = ((const float4*)attn)[sub];

    int a0 = __ldg(emi + instA * 3);
    int a1 = __ldg(emi + instA * 3 + 1);
    int a2 = __ldg(emi + instA * 3 + 2);
    int b0i = __ldg(emi + instB * 3);
    int b1i = __ldg(emi + instB * 3 + 1);
    int b2i = __ldg(emi + instB * 3 + 2);
    int tA = __ldg(tgt + instA);
    int tB = __ldg(tgt + instB);

    const uint2* feat2 = (const uint2*)g_feat_h;
    float4 vA0 = ldg_feat_h(feat2, (size_t)a0 * 16 + sub);
    float4 vA1 = ldg_feat_h(feat2, (size_t)a1 * 16 + sub);
    float4 vA2 = ldg_feat_h(feat2, (size_t)a2 * 16 + sub);
    float4 vB0 = ldg_feat_h(feat2, (size_t)b0i * 16 + sub);
    float4 vB1 = ldg_feat_h(feat2, (size_t)b1i * 16 + sub);
    float4 vB2 = ldg_feat_h(feat2, (size_t)b2i * 16 + sub);

    const float inv3 = (1.f / 3.f);

    {
        float hx = (vA0.x * fr0.x - vA0.y * fr0.y) + (vA1.x * fr1.x - vA1.y * fr1.y) + (vA2.x * fr2.x - vA2.y * fr2.y);
        float hy = (vA0.x * fr0.y + vA0.y * fr0.x) + (vA1.x * fr1.y + vA1.y * fr1.x) + (vA2.x * fr2.y + vA2.y * fr2.x);
        float hz = (vA0.z * fr0.z - vA0.w * fr0.w) + (vA1.z * fr1.z - vA1.w * fr1.w) + (vA2.z * fr2.z - vA2.w * fr2.w);
        float hw = (vA0.z * fr0.w + vA0.w * fr0.z) + (vA1.z * fr1.w + vA1.w * fr1.z) + (vA2.z * fr2.w + vA2.w * fr2.z);
        hx *= inv3; hy *= inv3; hz *= inv3; hw *= inv3;

        float p = hx * av.x + hy * av.y + hz * av.z + hw * av.w;
        p += __shfl_xor_sync(0xffffffffu, p, 1);
        float e = p > 0.f ? p : 0.01f * p;
        float a = expf(e);

        size_t base = (size_t)mp * BATCH + tA;
        if (!(sub & 1)) atomicAdd(&g_s[base * NHEAD + (sub >> 1)], a);
        float* rb = g_ret + base * HID + sub * 4;
        asm volatile("red.global.add.v4.f32 [%0], {%1, %2, %3, %4};"
                     :: "l"(rb), "f"(a * hx), "f"(a * hy), "f"(a * hz), "f"(a * hw)
                     : "memory");
    }
    {
        float hx = (vB0.x * fr0.x - vB0.y * fr0.y) + (vB1.x * fr1.x - vB1.y * fr1.y) + (vB2.x * fr2.x - vB2.y * fr2.y);
        float hy = (vB0.x * fr0.y + vB0.y * fr0.x) + (vB1.x * fr1.y + vB1.y * fr1.x) + (vB2.x * fr2.y + vB2.y * fr2.x);
        float hz = (vB0.z * fr0.z - vB0.w * fr0.w) + (vB1.z * fr1.z - vB1.w * fr1.w) + (vB2.z * fr2.z - vB2.w * fr2.w);
        float hw = (vB0.z * fr0.w + vB0.w * fr0.z) + (vB1.z * fr1.w + vB1.w * fr1.z) + (vB2.z * fr2.w + vB2.w * fr2.z);
        hx *= inv3; hy *= inv3; hz *= inv3; hw *= inv3;

        float p = hx * av.x + hy * av.y + hz * av.z + hw * av.w;
        p += __shfl_xor_sync(0xffffffffu, p, 1);
        float e = p > 0.f ? p : 0.01f * p;
        float a = expf(e);

        size_t base = (size_t)mp * BATCH + tB;
        if (!(sub & 1)) atomicAdd(&g_s[base * NHEAD + (sub >> 1)], a);
        float* rb = g_ret + base * HID + sub * 4;
        asm volatile("red.global.add.v4.f32 [%0], {%1, %2, %3, %4};"
                     :: "l"(rb), "f"(a * hx), "f"(a * hy), "f"(a * hz), "f"(a * hw)
                     : "memory");
    }
}

// ---------------- fused normalize+elu+mpout + semantic GEMV (R9: col-pair f32x2) ----------------
#define NSEM_BB  32
#define NSEM_BBP 33
#define NSEM_SMEM ((HID * AV_DIM + HID * NSEM_BBP) * 4)
__global__ void __launch_bounds__(256) k_normsem(
    int mp,
    const float* __restrict__ w1, const float* __restrict__ b1, const float* __restrict__ w2)
{
    int tid = threadIdx.x;
    extern __shared__ float dsm[];
    float* w1s = dsm;
    float* hs  = dsm + HID * AV_DIM;
    __shared__ float rbuf[8];

    for (int i = tid; i < HID * AV_DIM; i += 256) w1s[i] = w1[i];

    int b0 = blockIdx.x * NSEM_BB;
    #pragma unroll
    for (int r = 0; r < 8; ++r) {
        int i = tid + r * 256;
        int bl = i >> 6, k = i & 63;
        size_t row = (size_t)mp * BATCH + b0 + bl;
        float sv = g_s[row * NHEAD + (k >> 3)];
        float v = g_ret[row * HID + k] / (sv + 1e-9f);
        v = v > 0.f ? v : expf(v) - 1.f;
        g_mpout[row * HID + k] = v;
        hs[k * NSEM_BBP + bl] = v;
    }
    __syncthreads();

    int bl = tid & 31, ch = tid >> 5;
    int c0 = ch * 16;
    ull accp[8];
    {
        float4 ba = __ldg((const float4*)(b1 + c0));
        float4 bb = __ldg((const float4*)(b1 + c0 + 4));
        float4 bc = __ldg((const float4*)(b1 + c0 + 8));
        float4 bd = __ldg((const float4*)(b1 + c0 + 12));
        accp[0] = pack2(ba.x, ba.y); accp[1] = pack2(ba.z, ba.w);
        accp[2] = pack2(bb.x, bb.y); accp[3] = pack2(bb.z, bb.w);
        accp[4] = pack2(bc.x, bc.y); accp[5] = pack2(bc.z, bc.w);
        accp[6] = pack2(bd.x, bd.y); accp[7] = pack2(bd.z, bd.w);
    }
    #pragma unroll 4
    for (int k = 0; k < HID; ++k) {
        float xv = hs[k * NSEM_BBP + bl];
        ull xvp = pack2(xv, xv);
        const float4* wr = (const float4*)(w1s + k * AV_DIM + c0);
        float4 wv0 = wr[0], wv1 = wr[1], wv2 = wr[2], wv3 = wr[3];
        ffma2(accp[0], xvp, pack2(wv0.x, wv0.y));
        ffma2(accp[1], xvp, pack2(wv0.z, wv0.w));
        ffma2(accp[2], xvp, pack2(wv1.x, wv1.y));
        ffma2(accp[3], xvp, pack2(wv1.z, wv1.w));
        ffma2(accp[4], xvp, pack2(wv2.x, wv2.y));
        ffma2(accp[5], xvp, pack2(wv2.z, wv2.w));
        ffma2(accp[6], xvp, pack2(wv3.x, wv3.y));
        ffma2(accp[7], xvp, pack2(wv3.z, wv3.w));
    }
    float ssum = 0.f;
    {
        float4 wa = __ldg((const float4*)(w2 + c0));
        float4 wb = __ldg((const float4*)(w2 + c0 + 4));
        float4 wc = __ldg((const float4*)(w2 + c0 + 8));
        float4 wd = __ldg((const float4*)(w2 + c0 + 12));
        float lo, hi;
        unpack2(accp[0], lo, hi); ssum += tanh_fast(lo) * wa.x + tanh_fast(hi) * wa.y;
        unpack2(accp[1], lo, hi); ssum += tanh_fast(lo) * wa.z + tanh_fast(hi) * wa.w;
        unpack2(accp[2], lo, hi); ssum += tanh_fast(lo) * wb.x + tanh_fast(hi) * wb.y;
        unpack2(accp[3], lo, hi); ssum += tanh_fast(lo) * wb.z + tanh_fast(hi) * wb.w;
        unpack2(accp[4], lo, hi); ssum += tanh_fast(lo) * wc.x + tanh_fast(hi) * wc.y;
        unpack2(accp[5], lo, hi); ssum += tanh_fast(lo) * wc.z + tanh_fast(hi) * wc.w;
        unpack2(accp[6], lo, hi); ssum += tanh_fast(lo) * wd.x + tanh_fast(hi) * wd.y;
        unpack2(accp[7], lo, hi); ssum += tanh_fast(lo) * wd.z + tanh_fast(hi) * wd.w;
    }
    #pragma unroll
    for (int o = 16; o > 0; o >>= 1) ssum += __shfl_xor_sync(0xffffffffu, ssum, o);
    if ((tid & 31) == 0) rbuf[tid >> 5] = ssum;
    __syncthreads();
    if (tid == 0) {
        float t = rbuf[0] + rbuf[1] + rbuf[2] + rbuf[3] + rbuf[4] + rbuf[5] + rbuf[6] + rbuf[7];
        atomicAdd(&g_sem[mp], t);
    }
}

// ---------------- semantic fusion + product MLP + softmax (R9) ----------------
#define KF_BB  32
#define KF_BBP 33
#define KF_SMEM ((HID * CH_DIM + HID * KF_BBP + 2 * 8 * KF_BB) * 4)
__global__ void __launch_bounds__(256) k_final(
    const float* __restrict__ cw1, const float* __restrict__ cb1,
    const float* __restrict__ cw2, float* __restrict__ out)
{
    int tid = threadIdx.x;
    extern __shared__ float dsm[];
    float* cw1s = dsm;
    float* xs   = dsm + HID * CH_DIM;
    float* pl0  = xs + HID * KF_BBP;
    float* pl1  = pl0 + 8 * KF_BB;

    for (int i = tid; i < HID * CH_DIM; i += 256) cw1s[i] = cw1[i];

    float s0 = g_sem[0] * (1.f / BATCH), s1 = g_sem[1] * (1.f / BATCH);
    float s2 = g_sem[2] * (1.f / BATCH), s3 = g_sem[3] * (1.f / BATCH);
    float mU = fmaxf(s0, s1), mI = fmaxf(s2, s3);
    float e0 = expf(s0 - mU), e1 = expf(s1 - mU);
    float e2 = expf(s2 - mI), e3 = expf(s3 - mI);
    float bu0 = e0 / (e0 + e1), bu1 = e1 / (e0 + e1);
    float bi0 = e2 / (e2 + e3), bi1 = e3 / (e2 + e3);

    int b0 = blockIdx.x * KF_BB;
    #pragma unroll
    for (int r = 0; r < 8; ++r) {
        int i = tid + r * 256;
        int bl = i >> 6, k = i & 63;
        size_t b = b0 + bl;
        float hu = bu0 * g_mpout[((size_t)0 * BATCH + b) * HID + k]
                 + bu1 * g_mpout[((size_t)1 * BATCH + b) * HID + k];
        float hi = bi0 * g_mpout[((size_t)2 * BATCH + b) * HID + k]
                 + bi1 * g_mpout[((size_t)3 * BATCH + b) * HID + k];
        xs[k * KF_BBP + bl] = hu * hi;
    }
    __syncthreads();

    int bl = tid & 31, ch = tid >> 5;
    int c0 = ch * 16;
    float l0 = 0.f, l1 = 0.f;
    #pragma unroll
    for (int cc = 0; cc < 16; cc += 4) {
        int c = c0 + cc;
        float4 bv = __ldg((const float4*)(cb1 + c));
        float a0 = bv.x, a1 = bv.y, a2 = bv.z, a3 = bv.w;
        #pragma unroll 8
        for (int k = 0; k < HID; ++k) {
            float xv = xs[k * KF_BBP + bl];
            float4 wv = *(const float4*)(cw1s + k * CH_DIM + c);
            a0 = fmaf(xv, wv.x, a0);
            a1 = fmaf(xv, wv.y, a1);
            a2 = fmaf(xv, wv.z, a2);
            a3 = fmaf(xv, wv.w, a3);
        }
        a0 = fmaxf(a0, 0.f); a1 = fmaxf(a1, 0.f);
        a2 = fmaxf(a2, 0.f); a3 = fmaxf(a3, 0.f);
        float4 wa = __ldg((const float4*)(cw2 + 2 * c));
        float4 wb = __ldg((const float4*)(cw2 + 2 * c + 4));
        l0 += a0 * wa.x + a1 * wa.z + a2 * wb.x + a3 * wb.z;
        l1 += a0 * wa.y + a1 * wa.w + a2 * wb.y + a3 * wb.w;
    }
    pl0[ch * KF_BB + bl] = l0;
    pl1[ch * KF_BB + bl] = l1;
    __syncthreads();
    if (ch == 0) {
        float L0 = 0.f, L1 = 0.f;
        #pragma unroll
        for (int c = 0; c < 8; ++c) { L0 += pl0[c * KF_BB + bl]; L1 += pl1[c * KF_BB + bl]; }
        float m = fmaxf(L0, L1);
        float a0 = expf(L0 - m), a1 = expf(L1 - m);
        float inv = 1.f / (a0 + a1);
        out[(b0 + bl) * 2 + 0] = a0 * inv;
        out[(b0 + bl) * 2 + 1] = a1 * inv;
    }
}

// ---------------- launch (2-stream pipeline, capture-fork pattern) ----------------
extern "C" void kernel_launch(void* const* d_in, const int* in_sizes, int n_in,
                              void* d_out, int out_size) {
    (void)in_sizes; (void)n_in; (void)out_size;
    const float* feats0 = (const float*)d_in[0];
    const float* feats1 = (const float*)d_in[1];
    const float* t0_pw = (const float*)d_in[2];
    const float* t0_pb = (const float*)d_in[3];
    const float* t0_w2 = (const float*)d_in[4];
    const float* t0_b2 = (const float*)d_in[5];
    const float* t0_g  = (const float*)d_in[6];
    const float* t0_be = (const float*)d_in[7];
    const float* t1_pw = (const float*)d_in[8];
    const float* t1_pb = (const float*)d_in[9];
    const float* t1_w2 = (const float*)d_in[10];
    const float* t1_b2 = (const float*)d_in[11];
    const float* t1_g  = (const float*)d_in[12];
    const float* t1_be = (const float*)d_in[13];
    const float* r_vec = (const float*)d_in[14];
    const float* attn_user = (const float*)d_in[15];
    const float* attn_item = (const float*)d_in[16];
    const float* su_w1 = (const float*)d_in[17];
    const float* su_b1 = (const float*)d_in[18];
    const float* su_w2 = (const float*)d_in[19];
    const float* si_w1 = (const float*)d_in[20];
    const float* si_b1 = (const float*)d_in[21];
    const float* si_w2 = (const float*)d_in[22];
    const float* cw1   = (const float*)d_in[23];
    const float* cb1   = (const float*)d_in[24];
    const float* cw2   = (const float*)d_in[25];
    const int* idx0 = (const int*)d_in[26];
    const int* idx1 = (const int*)d_in[27];
    const int* emi_user = (const int*)d_in[28];
    const int* tgt_user = (const int*)d_in[29];
    const int* emi_item = (const int*)d_in[30];
    const int* tgt_item = (const int*)d_in[31];
    float* out = (float*)d_out;

    static cudaStream_t s1 = nullptr;
    static cudaEvent_t evRoot = nullptr, evPre = nullptr, evTow = nullptr, evS1 = nullptr;
    if (!s1) {
        cudaStreamCreateWithFlags(&s1, cudaStreamNonBlocking);
        cudaEventCreateWithFlags(&evRoot, cudaEventDisableTiming);
        cudaEventCreateWithFlags(&evPre,  cudaEventDisableTiming);
        cudaEventCreateWithFlags(&evTow,  cudaEventDisableTiming);
        cudaEventCreateWithFlags(&evS1,   cudaEventDisableTiming);
        cudaFuncSetAttribute(k_tower, cudaFuncAttributeMaxDynamicSharedMemorySize, TOW_SMEM);
        cudaFuncSetAttribute(k_normsem, cudaFuncAttributeMaxDynamicSharedMemorySize, NSEM_SMEM);
        cudaFuncSetAttribute(k_final, cudaFuncAttributeMaxDynamicSharedMemorySize, KF_SMEM);
    }

    void* p_s; void* p_ret; void* p_sem;
    cudaGetSymbolAddress(&p_s, g_s);
    cudaGetSymbolAddress(&p_ret, g_ret);
    cudaGetSymbolAddress(&p_sem, g_sem);

    cudaEventRecord(evRoot, 0);
    cudaStreamWaitEvent(s1, evRoot, 0);

    cudaMemsetAsync(p_s, 0, 4 * BATCH * NHEAD * sizeof(float), s1);
    cudaMemsetAsync(p_ret, 0, (size_t)4 * BATCH * HID * sizeof(float), s1);
    cudaMemsetAsync(p_sem, 0, 4 * sizeof(float), s1);
    k_fr<<<1, 128, 0, s1>>>(r_vec);
    cudaEventRecord(evPre, s1);

    dim3 tg((N0_NODES + TOW_BM - 1) / TOW_BM, 2);
    k_tower<<<tg, 256, TOW_SMEM, 0>>>(feats0, feats1,
        t0_pw, t0_pb, t0_w2, t0_b2, t0_g, t0_be,
        t1_pw, t1_pb, t1_w2, t1_b2, t1_g, t1_be,
        idx0, idx1);

    cudaStreamWaitEvent(0, evPre, 0);
    cudaEventRecord(evTow, 0);
    cudaStreamWaitEvent(s1, evTow, 0);

    const int* emiP[4] = { emi_user, emi_user + (size_t)E_CNT * 3, emi_item, emi_item + (size_t)E_CNT * 3 };
    const int* tgtP[4] = { tgt_user, tgt_user + E_CNT, tgt_item, tgt_item + E_CNT };
    const float* attnP[4] = { attn_user, attn_user + HID, attn_item, attn_item + HID };
    const float* w1P[4] = { su_w1, su_w1, si_w1, si_w1 };
    const float* b1P[4] = { su_b1, su_b1, si_b1, si_b1 };
    const float* w2P[4] = { su_w2, su_w2, si_w2, si_w2 };

    dim3 mg(E_CNT / 32);
    dim3 ng(BATCH / NSEM_BB);
    for (int mp = 0; mp < 4; ++mp) {
        cudaStream_t st = (mp & 1) ? s1 : (cudaStream_t)0;
        k_metapath<<<mg, 256, 0, st>>>(mp, emiP[mp], tgtP[mp], attnP[mp]);
        k_normsem<<<ng, 256, NSEM_SMEM, st>>>(mp, w1P[mp], b1P[mp], w2P[mp]);
    }

    cudaEventRecord(evS1, s1);
    cudaStreamWaitEvent(0, evS1, 0);
    k_final<<<BATCH / KF_BB, 256, KF_SMEM, 0>>>(cw1, cb1, cw2, out);
}